// round 10
// baseline (speedup 1.0000x reference)
#include <cuda_runtime.h>

// ---------------------------------------------------------------------------
// WindowGrapherPyg fused kernel, R9: barrier-free tensor-core GEMMs with
// (2 m-groups x 8 col-groups) warp decomposition: each warp = 32 rows x 24
// cols (2 m16 tiles x 3 n-tiles). Halves redundant B-fragment L1 traffic vs
// R8's (4x4) layout: 1.11 L1-wavefronts per MMA instead of 1.56.
// W pre-split (tf32 hi/lo) + pre-packed into per-lane fragment order.
// m16n8k8 fragment map (lane = 4*g+tig):
//   A: a0=(g,k=tig) a1=(g+8,tig) a2=(g,tig+4) a3=(g+8,tig+4)
//   B: b0=(k=tig,n=g) b1=(k=tig+4,n=g)
//   D: c0=(g,2tig) c1=(g,2tig+1) c2=(g+8,2tig) c3=(g+8,2tig+1)
// ---------------------------------------------------------------------------

typedef unsigned long long u64;

namespace {
constexpr int Bc = 2, Cc = 192, Hc = 192, Wc = 192;
constexpr int WS = 8, NN = 64, KK = 9, HEADS = 8, DH = 24;
constexpr int NWH = Hc / WS, NWW = Wc / WS;         // 24 x 24
constexpr int WB = Bc * NWH * NWW;                  // 1152 windows
constexpr int STR = 196;                            // xw/Q/K/V row stride
constexpr int NT = 512;
constexpr int XW_FLOATS = NN * STR;                 // 12544
constexpr int NTILES = Cc / 8;                      // 24 n-tiles
constexpr int KCH = Cc / 8;                         // 24 k-chunks
constexpr int FRAG_PER_MAT = NTILES * KCH * 32;     // 18432 float4
constexpr size_t SMEM_BYTES =
    (size_t)(4 * XW_FLOATS + NN * NN + NN) * sizeof(float) +
    (size_t)(NN * KK) * sizeof(int);                // 219,648 B
constexpr float INV_SQRT_DH = 0.20412414523193154f;
}

// Pre-packed tf32 hi/lo B fragments: [mat][ntile][kchunk][lane] float4.
__device__ float4 g_Wfrag[4 * FRAG_PER_MAT];

__device__ __forceinline__ u64 pack2f(float x, float y) {
  u64 r; asm("mov.b64 %0, {%1, %2};" : "=l"(r) : "f"(x), "f"(y)); return r;
}
__device__ __forceinline__ void fma2(u64& d, u64 a, u64 b) {
  asm("fma.rn.f32x2 %0, %1, %2, %0;" : "+l"(d) : "l"(a), "l"(b));
}
__device__ __forceinline__ float hsum2(u64 v) {
  float2 o; asm("mov.b64 {%0, %1}, %2;" : "=f"(o.x), "=f"(o.y) : "l"(v));
  return o.x + o.y;
}
__device__ __forceinline__ unsigned cvt_tf32(float f) {
  unsigned r; asm("cvt.rna.tf32.f32 %0, %1;" : "=r"(r) : "f"(f)); return r;
}
__device__ __forceinline__ void split_tf32(float f, unsigned& hi, unsigned& lo) {
  hi = cvt_tf32(f);
  lo = cvt_tf32(f - __uint_as_float(hi));
}
__device__ __forceinline__ void mma_tf32(float d[4], unsigned a0, unsigned a1,
                                         unsigned a2, unsigned a3,
                                         unsigned b0, unsigned b1) {
  asm("mma.sync.aligned.m16n8k8.row.col.f32.tf32.tf32.f32 "
      "{%0,%1,%2,%3}, {%4,%5,%6,%7}, {%8,%9}, {%0,%1,%2,%3};"
      : "+f"(d[0]), "+f"(d[1]), "+f"(d[2]), "+f"(d[3])
      : "r"(a0), "r"(a1), "r"(a2), "r"(a3), "r"(b0), "r"(b1));
}

// Prologue: pack W[k][n] into per-lane fragment float4s (see R8).
__global__ void pack_w_kernel(const float* __restrict__ w0,
                              const float* __restrict__ w1,
                              const float* __restrict__ w2,
                              const float* __restrict__ w3) {
  int i = blockIdx.x * blockDim.x + threadIdx.x;
  if (i >= 4 * FRAG_PER_MAT) return;
  int lane = i & 31;
  int t = i >> 5;
  int kc = t % KCH; t /= KCH;
  int ntile = t % NTILES;
  int mat = t / NTILES;
  const float* W = (mat == 0) ? w0 : (mat == 1) ? w1 : (mat == 2) ? w2 : w3;
  int n = ntile * 8 + (lane >> 2);
  int k0 = kc * 8 + (lane & 3);
  unsigned h0, l0, h1, l1;
  split_tf32(W[k0 * Cc + n], h0, l0);
  split_tf32(W[(k0 + 4) * Cc + n], h1, l1);
  g_Wfrag[i] = make_float4(__uint_as_float(h0), __uint_as_float(h1),
                           __uint_as_float(l0), __uint_as_float(l1));
}

// Warp grid: mtp = warp>>3 (rows mtp*32..+31, two m16 tiles), wg = warp&7
// (cols wg*24..+23, three n-tiles). acc[2][3][4]. Zero barriers.
__device__ __forceinline__ void gemm_core(const float* __restrict__ sXW,
                                          const float4* __restrict__ wf,
                                          float acc[2][3][4], int tid) {
  const int warp = tid >> 5, lane = tid & 31;
  const int g = lane >> 2, tig = lane & 3;
  const int mtp = warp >> 3, wg = warp & 7;
#pragma unroll
  for (int mi = 0; mi < 2; mi++)
#pragma unroll
    for (int j = 0; j < 3; j++)
#pragma unroll
      for (int q = 0; q < 4; q++) acc[mi][j][q] = 0.0f;

  const float4* wfb = wf + (wg * 3) * (KCH * 32) + lane;
  float4 bf[3];
#pragma unroll
  for (int j = 0; j < 3; j++) bf[j] = wfb[j * (KCH * 32)];

  const float* ap0 = sXW + (mtp * 32 + g) * STR + tig;
#pragma unroll 2
  for (int kc = 0; kc < KCH; kc++) {
    const float* ap = ap0 + kc * 8;
    unsigned ah[2][4], al[2][4];
#pragma unroll
    for (int mi = 0; mi < 2; mi++) {
      const float* am = ap + mi * 16 * STR;
      split_tf32(am[0],           ah[mi][0], al[mi][0]);
      split_tf32(am[8 * STR],     ah[mi][1], al[mi][1]);
      split_tf32(am[4],           ah[mi][2], al[mi][2]);
      split_tf32(am[8 * STR + 4], ah[mi][3], al[mi][3]);
    }
    float4 cur[3];
#pragma unroll
    for (int j = 0; j < 3; j++) cur[j] = bf[j];
    int kn = (kc + 1 < KCH) ? kc + 1 : 0;  // harmless wrap prefetch
#pragma unroll
    for (int j = 0; j < 3; j++) bf[j] = wfb[j * (KCH * 32) + kn * 32];
#pragma unroll
    for (int j = 0; j < 3; j++) {
      unsigned bh0 = __float_as_uint(cur[j].x);
      unsigned bh1 = __float_as_uint(cur[j].y);
      unsigned bl0 = __float_as_uint(cur[j].z);
      unsigned bl1 = __float_as_uint(cur[j].w);
#pragma unroll
      for (int mi = 0; mi < 2; mi++) {
        mma_tf32(acc[mi][j], ah[mi][0], ah[mi][1], ah[mi][2], ah[mi][3], bh0, bh1);
        mma_tf32(acc[mi][j], ah[mi][0], ah[mi][1], ah[mi][2], ah[mi][3], bl0, bl1);
        mma_tf32(acc[mi][j], al[mi][0], al[mi][1], al[mi][2], al[mi][3], bh0, bh1);
      }
    }
  }
}

__device__ __forceinline__ void gemm_to_smem(const float* __restrict__ sXW,
                                             const float4* __restrict__ wf,
                                             const float* __restrict__ bias,
                                             float* __restrict__ dst, int tid) {
  float acc[2][3][4];
  gemm_core(sXW, wf, acc, tid);
  const int warp = tid >> 5, lane = tid & 31;
  const int g = lane >> 2, tig = lane & 3;
  const int mtp = warp >> 3, wg = warp & 7;
#pragma unroll
  for (int mi = 0; mi < 2; mi++) {
    const int r0 = mtp * 32 + mi * 16 + g;
#pragma unroll
    for (int j = 0; j < 3; j++) {
      const int c = wg * 24 + 8 * j + 2 * tig;
      float2 bj = *(const float2*)(bias + c);
      *(float2*)(dst + r0 * STR + c) =
          make_float2(acc[mi][j][0] + bj.x, acc[mi][j][1] + bj.y);
      *(float2*)(dst + (r0 + 8) * STR + c) =
          make_float2(acc[mi][j][2] + bj.x, acc[mi][j][3] + bj.y);
    }
  }
}

__device__ __forceinline__ void gemm_skip_out(const float* __restrict__ sXW,
                                              const float4* __restrict__ wf,
                                              const float* __restrict__ bias,
                                              const float* __restrict__ sAttn,
                                              float* __restrict__ out,
                                              int b, int h0, int w0, int tid) {
  float acc[2][3][4];
  gemm_core(sXW, wf, acc, tid);
  const int warp = tid >> 5, lane = tid & 31;
  const int g = lane >> 2, tig = lane & 3;
  const int mtp = warp >> 3, wg = warp & 7;
#pragma unroll
  for (int mi = 0; mi < 2; mi++) {
    const int r0 = mtp * 32 + mi * 16 + g;   // node (nh0, nw=g)
    const int r1 = r0 + 8;                   // node (nh0+1, nw=g)
    const int nh0 = mtp * 4 + mi * 2;
    const long hw0 = (long)(h0 + nh0) * Wc + w0 + g;
    const long hw1 = hw0 + Wc;
#pragma unroll
    for (int j = 0; j < 3; j++) {
      const int c = wg * 24 + 8 * j + 2 * tig;
      float2 bj = *(const float2*)(bias + c);
      float v00 = acc[mi][j][0] + bj.x + sAttn[r0 * STR + c];
      float v01 = acc[mi][j][1] + bj.y + sAttn[r0 * STR + c + 1];
      float v10 = acc[mi][j][2] + bj.x + sAttn[r1 * STR + c];
      float v11 = acc[mi][j][3] + bj.y + sAttn[r1 * STR + c + 1];
      float* base0 = out + (long)(b * Cc + c) * Hc * Wc;
      float* base1 = out + (long)(b * Cc + c + 1) * Hc * Wc;
      base0[hw0] = v00; base1[hw0] = v01;
      base0[hw1] = v10; base1[hw1] = v11;
    }
  }
}

__global__ void __launch_bounds__(NT, 1)
wg_kernel(const float* __restrict__ x,
          const float* __restrict__ bq, const float* __restrict__ bk,
          const float* __restrict__ bv, const float* __restrict__ bsk,
          float* __restrict__ out) {
  extern __shared__ float sm[];
  float* sXW = sm;
  float* sQ = sXW + XW_FLOATS;
  float* sK = sQ + XW_FLOATS;
  float* sV = sK + XW_FLOATS;
  float* sG = sV + XW_FLOATS;    // 4096 floats
  float* sSq = sG + NN * NN;     // 64 floats
  int* sIdx = (int*)(sSq + NN);  // 64*9 ints

  const int tid = threadIdx.x;
  const int w = blockIdx.x;
  const int b = w / (NWH * NWW);
  const int rem = w - b * (NWH * NWW);
  const int wh = rem / NWW, ww = rem - wh * NWW;
  const int h0 = wh * WS, w0 = ww * WS;

  // ---- Phase A: gather window nodes ----
#pragma unroll
  for (int i = 0; i < 3; i++) {
    int t = tid + NT * i;          // 0..1535 : (c, nh)
    int c = t >> 3, nh = t & 7;
    const float* src = x + ((b * Cc + c) * Hc + h0 + nh) * Wc + w0;
    float4 v0 = *(const float4*)src;
    float4 v1 = *(const float4*)(src + 4);
    float* d = sXW + (nh * 8) * STR + c;
    d[0 * STR] = v0.x; d[1 * STR] = v0.y; d[2 * STR] = v0.z; d[3 * STR] = v0.w;
    d[4 * STR] = v1.x; d[5 * STR] = v1.y; d[6 * STR] = v1.z; d[7 * STR] = v1.w;
  }
  __syncthreads();

  // ---- Phase B1: Gram matrix (exact fp32), 1 row x 8 cols per thread ----
  {
    const int tn = tid >> 3;        // 0..63 (row)
    const int tm8 = tid & 7;        // cols tm8 + 8j
    u64 acc2[8];
#pragma unroll
    for (int j = 0; j < 8; j++) acc2[j] = 0ull;
    const float* ar = sXW + tn * STR;
#pragma unroll 2
    for (int k = 0; k < Cc; k += 4) {
      float4 a = *(const float4*)(ar + k);
      u64 alo = pack2f(a.x, a.y), ahi = pack2f(a.z, a.w);
#pragma unroll
      for (int j = 0; j < 8; j++) {
        float4 bb = *(const float4*)(sXW + (tm8 + 8 * j) * STR + k);
        fma2(acc2[j], alo, pack2f(bb.x, bb.y));
        fma2(acc2[j], ahi, pack2f(bb.z, bb.w));
      }
    }
#pragma unroll
    for (int j = 0; j < 8; j++)
      sG[tn * NN + tm8 + 8 * j] = hsum2(acc2[j]);
  }
  __syncthreads();
  if (tid < NN) sSq[tid] = sG[tid * (NN + 1)];
  __syncthreads();

  // ---- Phase B2: top-9 nearest neighbors (stable, exact fp32) ----
  if (tid < NN) {
    const int n = tid;
    unsigned long long mask = 1ull << n;  // exclude self
    const float sqn = sSq[n];
    const float* grow = sG + n * NN;
#pragma unroll 1
    for (int kk = 0; kk < KK; kk++) {
      float best = 3.0e38f;
      int bi = 0;
#pragma unroll 4
      for (int m = 0; m < NN; m++) {
        float d = sqn + sSq[m] - 2.0f * grow[m];
        if ((mask >> m) & 1ull) d = 3.9e38f;
        if (d < best) { best = d; bi = m; }  // '<' = lowest index wins ties
      }
      mask |= 1ull << bi;
      sIdx[n * KK + kk] = bi;
    }
  }

  // ---- Phase C: Q, K, V projections (tensor core, barrier-free) ----
  gemm_to_smem(sXW, g_Wfrag + 0 * FRAG_PER_MAT, bq, sQ, tid);
  gemm_to_smem(sXW, g_Wfrag + 1 * FRAG_PER_MAT, bk, sK, tid);
  gemm_to_smem(sXW, g_Wfrag + 2 * FRAG_PER_MAT, bv, sV, tid);
  __syncthreads();  // sQ/sK/sV (and sIdx) visible before attention

  // ---- Phase D: 9-neighbor softmax attention; 512 thr = one (n,h) each ----
  {
    const int n = tid & (NN - 1);
    const int h = tid >> 6;
    const float* qp = sQ + n * STR + h * DH;
    float q[DH];
#pragma unroll
    for (int d4 = 0; d4 < DH / 4; d4++) {
      float4 v = *(const float4*)(qp + d4 * 4);
      q[d4 * 4 + 0] = v.x; q[d4 * 4 + 1] = v.y;
      q[d4 * 4 + 2] = v.z; q[d4 * 4 + 3] = v.w;
    }
    float sc[KK];
    int nb[KK];
#pragma unroll
    for (int kk = 0; kk < KK; kk++) {
      int m = sIdx[n * KK + kk];
      nb[kk] = m;
      const float* kp = sK + m * STR + h * DH;
      float s = 0.0f;
#pragma unroll
      for (int d4 = 0; d4 < DH / 4; d4++) {
        float4 v = *(const float4*)(kp + d4 * 4);
        s = fmaf(q[d4 * 4 + 0], v.x, s);
        s = fmaf(q[d4 * 4 + 1], v.y, s);
        s = fmaf(q[d4 * 4 + 2], v.z, s);
        s = fmaf(q[d4 * 4 + 3], v.w, s);
      }
      sc[kk] = s * INV_SQRT_DH;
    }
    float mx = sc[0];
#pragma unroll
    for (int kk = 1; kk < KK; kk++) mx = fmaxf(mx, sc[kk]);
    float ssum = 0.0f;
#pragma unroll
    for (int kk = 0; kk < KK; kk++) { sc[kk] = __expf(sc[kk] - mx); ssum += sc[kk]; }
    const float inv = 1.0f / ssum;
    float o[DH] = {};
#pragma unroll
    for (int kk = 0; kk < KK; kk++) {
      float a = sc[kk] * inv;
      const float* vp = sV + nb[kk] * STR + h * DH;
#pragma unroll
      for (int d4 = 0; d4 < DH / 4; d4++) {
        float4 v = *(const float4*)(vp + d4 * 4);
        o[d4 * 4 + 0] = fmaf(a, v.x, o[d4 * 4 + 0]);
        o[d4 * 4 + 1] = fmaf(a, v.y, o[d4 * 4 + 1]);
        o[d4 * 4 + 2] = fmaf(a, v.z, o[d4 * 4 + 2]);
        o[d4 * 4 + 3] = fmaf(a, v.w, o[d4 * 4 + 3]);
      }
    }
    float* op = sQ + n * STR + h * DH;  // attn out overwrites own q segment
#pragma unroll
    for (int d4 = 0; d4 < DH / 4; d4++)
      *(float4*)(op + d4 * 4) =
          make_float4(o[d4 * 4 + 0], o[d4 * 4 + 1], o[d4 * 4 + 2], o[d4 * 4 + 3]);
  }
  __syncthreads();  // attn results in sQ visible before skip epilogue reads

  // ---- Phase E: skip GEMM + attn add + scatter to [B,C,H,W] ----
  gemm_skip_out(sXW, g_Wfrag + 3 * FRAG_PER_MAT, bsk, sQ, out, b, h0, w0, tid);
}

extern "C" void kernel_launch(void* const* d_in, const int* in_sizes, int n_in,
                              void* d_out, int out_size) {
  const float* x   = (const float*)d_in[0];
  const float* Wq  = (const float*)d_in[1];
  const float* bq  = (const float*)d_in[2];
  const float* Wk  = (const float*)d_in[3];
  const float* bk  = (const float*)d_in[4];
  const float* Wv  = (const float*)d_in[5];
  const float* bv  = (const float*)d_in[6];
  const float* Wsk = (const float*)d_in[7];
  const float* bsk = (const float*)d_in[8];
  float* out = (float*)d_out;

  pack_w_kernel<<<(4 * FRAG_PER_MAT + 255) / 256, 256>>>(Wq, Wk, Wv, Wsk);

  cudaFuncSetAttribute(wg_kernel, cudaFuncAttributeMaxDynamicSharedMemorySize,
                       (int)SMEM_BYTES);
  wg_kernel<<<WB, NT, SMEM_BYTES>>>(x, bq, bk, bv, bsk, out);
}

// round 11
// speedup vs baseline: 1.0003x; 1.0003x over previous
#include <cuda_runtime.h>
#include <cuda_bf16.h>

// ---------------------------------------------------------------------------
// WindowGrapherPyg fused kernel, R10: barrier-free tensor-core GEMMs,
// (2 m-groups x 8 col-groups) warp grid (halved B traffic, R9) PLUS
// one-shot A split: after exact-fp32 Gram/KNN, xw is split in place into
// tf32-hi (fp32 bits) and bf16 lo-pairs (aliasing the dead Gram buffer).
// GEMM inner loop: plain LDS for A (1 SHL + 1 AND per lo pair, zero cvt),
// coalesced LDG.128 B fragments (pre-split/pre-packed in global), 18 MMAs
// per k-chunk, zero __syncthreads inside GEMMs.
// m16n8k8 fragment map (lane = 4*g+tig):
//   A: a0=(g,k=tig) a1=(g+8,tig) a2=(g,tig+4) a3=(g+8,tig+4)
//   B: b0=(k=tig,n=g) b1=(k=tig+4,n=g)
//   D: c0=(g,2tig) c1=(g,2tig+1) c2=(g+8,2tig) c3=(g+8,2tig+1)
// ---------------------------------------------------------------------------

typedef unsigned long long u64;
typedef unsigned int u32;

namespace {
constexpr int Bc = 2, Cc = 192, Hc = 192, Wc = 192;
constexpr int WS = 8, NN = 64, KK = 9, HEADS = 8, DH = 24;
constexpr int NWH = Hc / WS, NWW = Wc / WS;         // 24 x 24
constexpr int WB = Bc * NWH * NWW;                  // 1152 windows
constexpr int STR = 196;                            // xw/Q/K/V row stride
constexpr int NT = 512;
constexpr int XW_FLOATS = NN * STR;                 // 12544
constexpr int NTILES = Cc / 8;                      // 24 n-tiles
constexpr int KCH = Cc / 8;                         // 24 k-chunks
constexpr int FRAG_PER_MAT = NTILES * KCH * 32;     // 18432 float4
constexpr int LOSTR = 100;                          // lo-pair row stride (u32)
constexpr int LO_U32 = NN * LOSTR;                  // 6400 (>= 4096 Gram alias)
constexpr size_t SMEM_BYTES =
    (size_t)(4 * XW_FLOATS + LO_U32 + NN) * sizeof(float) +
    (size_t)(NN * KK) * sizeof(int);                // 228,864 B
constexpr float INV_SQRT_DH = 0.20412414523193154f;
}

// Pre-packed tf32 hi/lo B fragments: [mat][ntile][kchunk][lane] float4.
__device__ float4 g_Wfrag[4 * FRAG_PER_MAT];

__device__ __forceinline__ u64 pack2f(float x, float y) {
  u64 r; asm("mov.b64 %0, {%1, %2};" : "=l"(r) : "f"(x), "f"(y)); return r;
}
__device__ __forceinline__ void fma2(u64& d, u64 a, u64 b) {
  asm("fma.rn.f32x2 %0, %1, %2, %0;" : "+l"(d) : "l"(a), "l"(b));
}
__device__ __forceinline__ float hsum2(u64 v) {
  float2 o; asm("mov.b64 {%0, %1}, %2;" : "=f"(o.x), "=f"(o.y) : "l"(v));
  return o.x + o.y;
}
__device__ __forceinline__ unsigned cvt_tf32(float f) {
  unsigned r; asm("cvt.rna.tf32.f32 %0, %1;" : "=r"(r) : "f"(f)); return r;
}
__device__ __forceinline__ void split_tf32(float f, unsigned& hi, unsigned& lo) {
  hi = cvt_tf32(f);
  lo = cvt_tf32(f - __uint_as_float(hi));
}
__device__ __forceinline__ void mma_tf32(float d[4], unsigned a0, unsigned a1,
                                         unsigned a2, unsigned a3,
                                         unsigned b0, unsigned b1) {
  asm("mma.sync.aligned.m16n8k8.row.col.f32.tf32.tf32.f32 "
      "{%0,%1,%2,%3}, {%4,%5,%6,%7}, {%8,%9}, {%0,%1,%2,%3};"
      : "+f"(d[0]), "+f"(d[1]), "+f"(d[2]), "+f"(d[3])
      : "r"(a0), "r"(a1), "r"(a2), "r"(a3), "r"(b0), "r"(b1));
}

// Prologue: pack W[k][n] into per-lane fragment float4s (see R8).
__global__ void pack_w_kernel(const float* __restrict__ w0,
                              const float* __restrict__ w1,
                              const float* __restrict__ w2,
                              const float* __restrict__ w3) {
  int i = blockIdx.x * blockDim.x + threadIdx.x;
  if (i >= 4 * FRAG_PER_MAT) return;
  int lane = i & 31;
  int t = i >> 5;
  int kc = t % KCH; t /= KCH;
  int ntile = t % NTILES;
  int mat = t / NTILES;
  const float* W = (mat == 0) ? w0 : (mat == 1) ? w1 : (mat == 2) ? w2 : w3;
  int n = ntile * 8 + (lane >> 2);
  int k0 = kc * 8 + (lane & 3);
  unsigned h0, l0, h1, l1;
  split_tf32(W[k0 * Cc + n], h0, l0);
  split_tf32(W[(k0 + 4) * Cc + n], h1, l1);
  g_Wfrag[i] = make_float4(__uint_as_float(h0), __uint_as_float(h1),
                           __uint_as_float(l0), __uint_as_float(l1));
}

// Warp grid: mtp = warp>>3 (rows mtp*32..+31), wg = warp&7 (cols wg*24..+23).
// A: hi from sXW (pre-split in place), lo from bf16 pair buffer.
__device__ __forceinline__ void gemm_core(const float* __restrict__ sXW,
                                          const u32* __restrict__ sLo,
                                          const float4* __restrict__ wf,
                                          float acc[2][3][4], int tid) {
  const int warp = tid >> 5, lane = tid & 31;
  const int g = lane >> 2, tig = lane & 3;
  const int mtp = warp >> 3, wg = warp & 7;
#pragma unroll
  for (int mi = 0; mi < 2; mi++)
#pragma unroll
    for (int j = 0; j < 3; j++)
#pragma unroll
      for (int q = 0; q < 4; q++) acc[mi][j][q] = 0.0f;

  const float4* wfb = wf + (wg * 3) * (KCH * 32) + lane;
  float4 bf[3];
#pragma unroll
  for (int j = 0; j < 3; j++) bf[j] = wfb[j * (KCH * 32)];

  const int r0 = mtp * 32 + g;
  const float* hp = sXW + r0 * STR + tig;
  const u32* lp = sLo + r0 * LOSTR + tig;
#pragma unroll 2
  for (int kc = 0; kc < KCH; kc++) {
    unsigned ah[2][4], al[2][4];
#pragma unroll
    for (int mi = 0; mi < 2; mi++) {
      const float* hm = hp + (mi * 16) * STR + kc * 8;
      ah[mi][0] = __float_as_uint(hm[0]);
      ah[mi][1] = __float_as_uint(hm[8 * STR]);
      ah[mi][2] = __float_as_uint(hm[4]);
      ah[mi][3] = __float_as_uint(hm[8 * STR + 4]);
      u32 p0 = lp[(mi * 16) * LOSTR + kc * 4];
      u32 p1 = lp[(mi * 16 + 8) * LOSTR + kc * 4];
      al[mi][0] = p0 << 16;           // bf16(lo[k0]) -> fp32/tf32 bits
      al[mi][2] = p0 & 0xFFFF0000u;   // bf16(lo[k0+4])
      al[mi][1] = p1 << 16;
      al[mi][3] = p1 & 0xFFFF0000u;
    }
    float4 cur[3];
#pragma unroll
    for (int j = 0; j < 3; j++) cur[j] = bf[j];
    int kn = (kc + 1 < KCH) ? kc + 1 : 0;  // harmless wrap prefetch
#pragma unroll
    for (int j = 0; j < 3; j++) bf[j] = wfb[j * (KCH * 32) + kn * 32];
#pragma unroll
    for (int j = 0; j < 3; j++) {
      unsigned bh0 = __float_as_uint(cur[j].x);
      unsigned bh1 = __float_as_uint(cur[j].y);
      unsigned bl0 = __float_as_uint(cur[j].z);
      unsigned bl1 = __float_as_uint(cur[j].w);
#pragma unroll
      for (int mi = 0; mi < 2; mi++) {
        mma_tf32(acc[mi][j], ah[mi][0], ah[mi][1], ah[mi][2], ah[mi][3], bh0, bh1);
        mma_tf32(acc[mi][j], ah[mi][0], ah[mi][1], ah[mi][2], ah[mi][3], bl0, bl1);
        mma_tf32(acc[mi][j], al[mi][0], al[mi][1], al[mi][2], al[mi][3], bh0, bh1);
      }
    }
  }
}

__device__ __forceinline__ void gemm_to_smem(const float* __restrict__ sXW,
                                             const u32* __restrict__ sLo,
                                             const float4* __restrict__ wf,
                                             const float* __restrict__ bias,
                                             float* __restrict__ dst, int tid) {
  float acc[2][3][4];
  gemm_core(sXW, sLo, wf, acc, tid);
  const int warp = tid >> 5, lane = tid & 31;
  const int g = lane >> 2, tig = lane & 3;
  const int mtp = warp >> 3, wg = warp & 7;
#pragma unroll
  for (int mi = 0; mi < 2; mi++) {
    const int r0 = mtp * 32 + mi * 16 + g;
#pragma unroll
    for (int j = 0; j < 3; j++) {
      const int c = wg * 24 + 8 * j + 2 * tig;
      float2 bj = *(const float2*)(bias + c);
      *(float2*)(dst + r0 * STR + c) =
          make_float2(acc[mi][j][0] + bj.x, acc[mi][j][1] + bj.y);
      *(float2*)(dst + (r0 + 8) * STR + c) =
          make_float2(acc[mi][j][2] + bj.x, acc[mi][j][3] + bj.y);
    }
  }
}

__device__ __forceinline__ void gemm_skip_out(const float* __restrict__ sXW,
                                              const u32* __restrict__ sLo,
                                              const float4* __restrict__ wf,
                                              const float* __restrict__ bias,
                                              const float* __restrict__ sAttn,
                                              float* __restrict__ out,
                                              int b, int h0, int w0, int tid) {
  float acc[2][3][4];
  gemm_core(sXW, sLo, wf, acc, tid);
  const int warp = tid >> 5, lane = tid & 31;
  const int g = lane >> 2, tig = lane & 3;
  const int mtp = warp >> 3, wg = warp & 7;
#pragma unroll
  for (int mi = 0; mi < 2; mi++) {
    const int r0 = mtp * 32 + mi * 16 + g;   // node (nh0, nw=g)
    const int r1 = r0 + 8;                   // node (nh0+1, nw=g)
    const int nh0 = mtp * 4 + mi * 2;
    const long hw0 = (long)(h0 + nh0) * Wc + w0 + g;
    const long hw1 = hw0 + Wc;
#pragma unroll
    for (int j = 0; j < 3; j++) {
      const int c = wg * 24 + 8 * j + 2 * tig;
      float2 bj = *(const float2*)(bias + c);
      float v00 = acc[mi][j][0] + bj.x + sAttn[r0 * STR + c];
      float v01 = acc[mi][j][1] + bj.y + sAttn[r0 * STR + c + 1];
      float v10 = acc[mi][j][2] + bj.x + sAttn[r1 * STR + c];
      float v11 = acc[mi][j][3] + bj.y + sAttn[r1 * STR + c + 1];
      float* base0 = out + (long)(b * Cc + c) * Hc * Wc;
      float* base1 = out + (long)(b * Cc + c + 1) * Hc * Wc;
      base0[hw0] = v00; base1[hw0] = v01;
      base0[hw1] = v10; base1[hw1] = v11;
    }
  }
}

__global__ void __launch_bounds__(NT, 1)
wg_kernel(const float* __restrict__ x,
          const float* __restrict__ bq, const float* __restrict__ bk,
          const float* __restrict__ bv, const float* __restrict__ bsk,
          float* __restrict__ out) {
  extern __shared__ float sm[];
  float* sXW = sm;               // exact xw, later tf32-hi in place
  float* sQ = sXW + XW_FLOATS;
  float* sK = sQ + XW_FLOATS;
  float* sV = sK + XW_FLOATS;
  u32* sLo = (u32*)(sV + XW_FLOATS);  // 6400 u32; first 4096 alias Gram
  float* sG = (float*)sLo;            // Gram (dead after KNN)
  float* sSq = (float*)(sLo + LO_U32);   // 64 floats
  int* sIdx = (int*)(sSq + NN);          // 64*9 ints

  const int tid = threadIdx.x;
  const int w = blockIdx.x;
  const int b = w / (NWH * NWW);
  const int rem = w - b * (NWH * NWW);
  const int wh = rem / NWW, ww = rem - wh * NWW;
  const int h0 = wh * WS, w0 = ww * WS;

  // ---- Phase A: gather window nodes ----
#pragma unroll
  for (int i = 0; i < 3; i++) {
    int t = tid + NT * i;          // 0..1535 : (c, nh)
    int c = t >> 3, nh = t & 7;
    const float* src = x + ((b * Cc + c) * Hc + h0 + nh) * Wc + w0;
    float4 v0 = *(const float4*)src;
    float4 v1 = *(const float4*)(src + 4);
    float* d = sXW + (nh * 8) * STR + c;
    d[0 * STR] = v0.x; d[1 * STR] = v0.y; d[2 * STR] = v0.z; d[3 * STR] = v0.w;
    d[4 * STR] = v1.x; d[5 * STR] = v1.y; d[6 * STR] = v1.z; d[7 * STR] = v1.w;
  }
  __syncthreads();

  // ---- Phase B1: Gram matrix (exact fp32), 1 row x 8 cols per thread ----
  {
    const int tn = tid >> 3;        // 0..63 (row)
    const int tm8 = tid & 7;        // cols tm8 + 8j
    u64 acc2[8];
#pragma unroll
    for (int j = 0; j < 8; j++) acc2[j] = 0ull;
    const float* ar = sXW + tn * STR;
#pragma unroll 2
    for (int k = 0; k < Cc; k += 4) {
      float4 a = *(const float4*)(ar + k);
      u64 alo = pack2f(a.x, a.y), ahi = pack2f(a.z, a.w);
#pragma unroll
      for (int j = 0; j < 8; j++) {
        float4 bb = *(const float4*)(sXW + (tm8 + 8 * j) * STR + k);
        fma2(acc2[j], alo, pack2f(bb.x, bb.y));
        fma2(acc2[j], ahi, pack2f(bb.z, bb.w));
      }
    }
#pragma unroll
    for (int j = 0; j < 8; j++)
      sG[tn * NN + tm8 + 8 * j] = hsum2(acc2[j]);
  }
  __syncthreads();
  if (tid < NN) sSq[tid] = sG[tid * (NN + 1)];
  __syncthreads();

  // ---- Phase B2: top-9 nearest neighbors (stable, exact fp32) ----
  if (tid < NN) {
    const int n = tid;
    unsigned long long mask = 1ull << n;  // exclude self
    const float sqn = sSq[n];
    const float* grow = sG + n * NN;
#pragma unroll 1
    for (int kk = 0; kk < KK; kk++) {
      float best = 3.0e38f;
      int bi = 0;
#pragma unroll 4
      for (int m = 0; m < NN; m++) {
        float d = sqn + sSq[m] - 2.0f * grow[m];
        if ((mask >> m) & 1ull) d = 3.9e38f;
        if (d < best) { best = d; bi = m; }  // '<' = lowest index wins ties
      }
      mask |= 1ull << bi;
      sIdx[n * KK + kk] = bi;
    }
  }
  __syncthreads();  // KNN done reading sG before sLo overwrites it

  // ---- Phase B3: split xw in place -> tf32 hi (sXW) + bf16 lo pairs ----
  // pair p <-> (row, kc, tig): covers k0 = kc*8+tig and k0+4.
#pragma unroll
  for (int i = 0; i < 12; i++) {
    int p = tid + NT * i;           // 0..6143
    int row = p / 96, pr = p - row * 96;
    int kc = pr >> 2, tg = pr & 3;
    int k0 = kc * 8 + tg;
    float* xr = sXW + row * STR;
    float f0 = xr[k0], f1 = xr[k0 + 4];
    unsigned h0 = cvt_tf32(f0);
    unsigned h1 = cvt_tf32(f1);
    float l0 = f0 - __uint_as_float(h0);
    float l1 = f1 - __uint_as_float(h1);
    xr[k0] = __uint_as_float(h0);
    xr[k0 + 4] = __uint_as_float(h1);
    u32 b0 = (u32)__bfloat16_as_ushort(__float2bfloat16_rn(l0));
    u32 b1 = (u32)__bfloat16_as_ushort(__float2bfloat16_rn(l1));
    sLo[row * LOSTR + kc * 4 + tg] = b0 | (b1 << 16);
  }
  __syncthreads();

  // ---- Phase C: Q, K, V projections (tensor core, barrier-free) ----
  gemm_to_smem(sXW, sLo, g_Wfrag + 0 * FRAG_PER_MAT, bq, sQ, tid);
  gemm_to_smem(sXW, sLo, g_Wfrag + 1 * FRAG_PER_MAT, bk, sK, tid);
  gemm_to_smem(sXW, sLo, g_Wfrag + 2 * FRAG_PER_MAT, bv, sV, tid);
  __syncthreads();  // sQ/sK/sV visible before attention

  // ---- Phase D: 9-neighbor softmax attention; 512 thr = one (n,h) each ----
  {
    const int n = tid & (NN - 1);
    const int h = tid >> 6;
    const float* qp = sQ + n * STR + h * DH;
    float q[DH];
#pragma unroll
    for (int d4 = 0; d4 < DH / 4; d4++) {
      float4 v = *(const float4*)(qp + d4 * 4);
      q[d4 * 4 + 0] = v.x; q[d4 * 4 + 1] = v.y;
      q[d4 * 4 + 2] = v.z; q[d4 * 4 + 3] = v.w;
    }
    float sc[KK];
    int nb[KK];
#pragma unroll
    for (int kk = 0; kk < KK; kk++) {
      int m = sIdx[n * KK + kk];
      nb[kk] = m;
      const float* kp = sK + m * STR + h * DH;
      float s = 0.0f;
#pragma unroll
      for (int d4 = 0; d4 < DH / 4; d4++) {
        float4 v = *(const float4*)(kp + d4 * 4);
        s = fmaf(q[d4 * 4 + 0], v.x, s);
        s = fmaf(q[d4 * 4 + 1], v.y, s);
        s = fmaf(q[d4 * 4 + 2], v.z, s);
        s = fmaf(q[d4 * 4 + 3], v.w, s);
      }
      sc[kk] = s * INV_SQRT_DH;
    }
    float mx = sc[0];
#pragma unroll
    for (int kk = 1; kk < KK; kk++) mx = fmaxf(mx, sc[kk]);
    float ssum = 0.0f;
#pragma unroll
    for (int kk = 0; kk < KK; kk++) { sc[kk] = __expf(sc[kk] - mx); ssum += sc[kk]; }
    const float inv = 1.0f / ssum;
    float o[DH] = {};
#pragma unroll
    for (int kk = 0; kk < KK; kk++) {
      float a = sc[kk] * inv;
      const float* vp = sV + nb[kk] * STR + h * DH;
#pragma unroll
      for (int d4 = 0; d4 < DH / 4; d4++) {
        float4 v = *(const float4*)(vp + d4 * 4);
        o[d4 * 4 + 0] = fmaf(a, v.x, o[d4 * 4 + 0]);
        o[d4 * 4 + 1] = fmaf(a, v.y, o[d4 * 4 + 1]);
        o[d4 * 4 + 2] = fmaf(a, v.z, o[d4 * 4 + 2]);
        o[d4 * 4 + 3] = fmaf(a, v.w, o[d4 * 4 + 3]);
      }
    }
    float* op = sQ + n * STR + h * DH;  // attn out overwrites own q segment
#pragma unroll
    for (int d4 = 0; d4 < DH / 4; d4++)
      *(float4*)(op + d4 * 4) =
          make_float4(o[d4 * 4 + 0], o[d4 * 4 + 1], o[d4 * 4 + 2], o[d4 * 4 + 3]);
  }
  __syncthreads();  // attn results in sQ visible before skip epilogue reads

  // ---- Phase E: skip GEMM + attn add + scatter to [B,C,H,W] ----
  gemm_skip_out(sXW, sLo, g_Wfrag + 3 * FRAG_PER_MAT, bsk, sQ, out,
                b, h0, w0, tid);
}

extern "C" void kernel_launch(void* const* d_in, const int* in_sizes, int n_in,
                              void* d_out, int out_size) {
  const float* x   = (const float*)d_in[0];
  const float* Wq  = (const float*)d_in[1];
  const float* bq  = (const float*)d_in[2];
  const float* Wk  = (const float*)d_in[3];
  const float* bk  = (const float*)d_in[4];
  const float* Wv  = (const float*)d_in[5];
  const float* bv  = (const float*)d_in[6];
  const float* Wsk = (const float*)d_in[7];
  const float* bsk = (const float*)d_in[8];
  float* out = (float*)d_out;

  pack_w_kernel<<<(4 * FRAG_PER_MAT + 255) / 256, 256>>>(Wq, Wk, Wv, Wsk);

  cudaFuncSetAttribute(wg_kernel, cudaFuncAttributeMaxDynamicSharedMemorySize,
                       (int)SMEM_BYTES);
  wg_kernel<<<WB, NT, SMEM_BYTES>>>(x, bq, bk, bv, bsk, out);
}